// round 15
// baseline (speedup 1.0000x reference)
#include <cuda_runtime.h>
#include <cuda_bf16.h>
#include <cuda_fp16.h>
#include <math.h>
#include <stdint.h>

#define NN_   10000
#define EE_   320000
#define ETOT  (EE_ + NN_)
#define H_    4
#define F_    256
#define HF_   1024
#define LEAKY 0.2f
#define CH    128
#define NTILE 79
#define TRI   (NTILE * (NTILE + 1) / 2)

// ---------------- scratch (device globals) ----------------------------------
__device__ float  g_h[(size_t)NN_ * HF_];          // fp32 h (layer 3)
__device__ __half g_h16[(size_t)NN_ * HF_];        // fp16 h (layers 0-2)
__device__ __align__(16) float g_als[2 * NN_ * H_];
__device__ __align__(16) float g_ald[2 * NN_ * H_];
__device__ float  g_zbuf[(size_t)NN_ * F_];
__device__ int    g_cnt[NN_];
__device__ int    g_off[NN_ + 1];
__device__ int    g_wpos[NN_];
__device__ int    g_srcs[ETOT];
__device__ __align__(16) __nv_bfloat16 g_bfh[(size_t)NN_ * F_];
__device__ __align__(16) __nv_bfloat16 g_bfl[(size_t)NN_ * F_];
__device__ __align__(16) __nv_bfloat16 g_wth[4 * (size_t)HF_ * F_];
__device__ __align__(16) __nv_bfloat16 g_wtl[4 * (size_t)HF_ * F_];

// ---------------- small PTX helpers -----------------------------------------
__device__ __forceinline__ uint32_t smem_u32(const void* p) {
    uint32_t a;
    asm("{ .reg .u64 t; cvta.to.shared.u64 t, %1; cvt.u32.u64 %0, t; }" : "=r"(a) : "l"(p));
    return a;
}
__device__ __forceinline__ void cp16(uint32_t dst, const void* src, bool valid) {
    int sz = valid ? 16 : 0;
    asm volatile("cp.async.cg.shared.global [%0], [%1], 16, %2;"
                 :: "r"(dst), "l"(src), "r"(sz) : "memory");
}
__device__ __forceinline__ void cp_commit() {
    asm volatile("cp.async.commit_group;" ::: "memory");
}
__device__ __forceinline__ void cp_wait1() {
    asm volatile("cp.async.wait_group 1;" ::: "memory");
}
__device__ __forceinline__ void ldsm4(uint32_t& r0, uint32_t& r1, uint32_t& r2,
                                      uint32_t& r3, uint32_t a) {
    asm volatile("ldmatrix.sync.aligned.m8n8.x4.shared.b16 {%0,%1,%2,%3}, [%4];"
                 : "=r"(r0), "=r"(r1), "=r"(r2), "=r"(r3) : "r"(a));
}
__device__ __forceinline__ void mma16816(float c[4], uint32_t a0, uint32_t a1,
                                         uint32_t a2, uint32_t a3,
                                         uint32_t b0, uint32_t b1) {
    asm volatile(
        "mma.sync.aligned.m16n8k16.row.col.f32.bf16.bf16.f32 "
        "{%0,%1,%2,%3}, {%4,%5,%6,%7}, {%8,%9}, {%0,%1,%2,%3};"
        : "+f"(c[0]), "+f"(c[1]), "+f"(c[2]), "+f"(c[3])
        : "r"(a0), "r"(a1), "r"(a2), "r"(a3), "r"(b0), "r"(b1));
}

// ---------------- CSR build -------------------------------------------------
__global__ void count_kernel(const int* __restrict__ ei) {
    int e = blockIdx.x * blockDim.x + threadIdx.x;
    if (e >= ETOT) return;
    int dst = (e < EE_) ? ei[EE_ + e] : (e - EE_);
    atomicAdd(&g_cnt[dst], 1);
}
__global__ void scan_kernel() {
    __shared__ int sh[1024];
    int tid = threadIdx.x;
    int carry = 0;
    for (int base = 0; base < NN_; base += 1024) {
        int v = (base + tid < NN_) ? g_cnt[base + tid] : 0;
        sh[tid] = v;
        __syncthreads();
        for (int d = 1; d < 1024; d <<= 1) {
            int t = (tid >= d) ? sh[tid - d] : 0;
            __syncthreads();
            sh[tid] += t;
            __syncthreads();
        }
        if (base + tid < NN_) g_off[base + tid] = carry + sh[tid] - v;
        int tot = sh[1023];
        __syncthreads();
        carry += tot;
    }
    if (tid == 0) g_off[NN_] = carry;
}
__global__ void scatter_kernel(const int* __restrict__ ei) {
    int e = blockIdx.x * blockDim.x + threadIdx.x;
    if (e >= ETOT) return;
    int src, dst;
    if (e < EE_) { src = ei[e]; dst = ei[EE_ + e]; }
    else         { src = e - EE_; dst = e - EE_; }
    int pos = g_off[dst] + atomicAdd(&g_wpos[dst], 1);
    g_srcs[pos] = src;
}

// ---------------- unified bf16-split HMMA GEMM ------------------------------
#define GBUF   32768
#define NSTAGE 3

__global__ __launch_bounds__(256) void hmma_tt(
    const __nv_bfloat16* __restrict__ Ah, const __nv_bfloat16* __restrict__ Al,
    const __nv_bfloat16* __restrict__ Bh, const __nv_bfloat16* __restrict__ Bl,
    const float* __restrict__ asrc, const float* __restrict__ adst,
    float* __restrict__ pals, float* __restrict__ pald,
    float* __restrict__ C, __half* __restrict__ C16,
    int M, int Ncols, size_t ldc, int mode)
{
    extern __shared__ char dyn_smem[];
    uint32_t smem_base = smem_u32(dyn_smem);

    int tid = threadIdx.x;
    int wid = tid >> 5, lane = tid & 31;
    int wm = wid >> 2, wn = wid & 3;
    int g = lane >> 2, t = lane & 3;

    int bx, by;
    if (mode == 2) {
        int j = blockIdx.x;
        bx = (int)((sqrtf(8.f * j + 1.f) - 1.f) * 0.5f);
        while ((bx + 1) * (bx + 2) / 2 <= j) bx++;
        while (bx * (bx + 1) / 2 > j) bx--;
        by = j - bx * (bx + 1) / 2;
    } else {
        bx = blockIdx.x; by = blockIdx.y;
    }
    int m0 = by * 128, n0 = bx * 128;

    const __nv_bfloat16* segA[3] = { Ah, Ah, Al };
    const __nv_bfloat16* segB[3] = { Bh, Bl, Bh };

    uint32_t l_off[4];
    size_t   l_arow[4], l_brow[4];
    bool     l_va[4], l_vb[4];
#pragma unroll
    for (int i = 0; i < 4; i++) {
        int idx = tid + i * 256;
        int r = idx >> 3, s16 = idx & 7;
        l_off[i] = (uint32_t)(r * 128 + ((s16 ^ (r & 7)) << 4));
        int gm = m0 + r, gn = n0 + r;
        l_va[i] = gm < M;
        l_vb[i] = gn < Ncols;
        l_arow[i] = (size_t)(l_va[i] ? gm : 0) * (F_ * 2) + (size_t)s16 * 16;
        l_brow[i] = (size_t)(l_vb[i] ? gn : 0) * (F_ * 2) + (size_t)s16 * 16;
    }

    float acc[4][4][4];
#pragma unroll
    for (int i = 0; i < 4; i++)
#pragma unroll
        for (int j2 = 0; j2 < 4; j2++)
#pragma unroll
            for (int k = 0; k < 4; k++) acc[i][j2][k] = 0.f;

    auto issue_chunk = [&](int c) {
        int seg = c >> 2;
        size_t kb = (size_t)((c & 3) * 64) * 2;
        const char* As = (const char*)segA[seg] + kb;
        const char* Bs = (const char*)segB[seg] + kb;
        uint32_t sa = smem_base + (c % NSTAGE) * GBUF;
        uint32_t sb = sa + 16384;
#pragma unroll
        for (int i = 0; i < 4; i++) {
            cp16(sa + l_off[i], As + l_arow[i], l_va[i]);
            cp16(sb + l_off[i], Bs + l_brow[i], l_vb[i]);
        }
        cp_commit();
    };

    issue_chunk(0);
    issue_chunk(1);

    int lr = lane & 15;
    uint32_t a_rowoff[4], b_rowoff[2];
    uint32_t rxa = (uint32_t)(lr & 7) << 4, lhalf = (uint32_t)(lane >> 4) << 4;
#pragma unroll
    for (int mt = 0; mt < 4; mt++)
        a_rowoff[mt] = (uint32_t)((wm * 64 + mt * 16 + lr) * 128);
#pragma unroll
    for (int hb = 0; hb < 2; hb++)
        b_rowoff[hb] = (uint32_t)((wn * 32 + hb * 16 + lr) * 128);

    for (int c = 0; c < 12; c++) {
        cp_wait1();
        __syncthreads();
        if (c + 2 < 12) issue_chunk(c + 2);

        uint32_t sa = smem_base + (c % NSTAGE) * GBUF;
        uint32_t sb = sa + 16384;
#pragma unroll
        for (int ks = 0; ks < 4; ks++) {
            uint32_t xr = ((uint32_t)(2 * ks) << 4) + lhalf;
            uint32_t af[4][4];
#pragma unroll
            for (int mt = 0; mt < 4; mt++)
                ldsm4(af[mt][0], af[mt][1], af[mt][2], af[mt][3],
                      sa + a_rowoff[mt] + (xr ^ rxa));
            uint32_t bq[2][4];
#pragma unroll
            for (int hb = 0; hb < 2; hb++)
                ldsm4(bq[hb][0], bq[hb][1], bq[hb][2], bq[hb][3],
                      sb + b_rowoff[hb] + (xr ^ rxa));
#pragma unroll
            for (int mt = 0; mt < 4; mt++)
#pragma unroll
                for (int nt = 0; nt < 4; nt++)
                    mma16816(acc[mt][nt],
                             af[mt][0], af[mt][1], af[mt][2], af[mt][3],
                             bq[nt >> 1][nt & 1], bq[nt >> 1][(nt & 1) + 2]);
        }
    }

    if (mode <= 1) {
        int head = n0 >> 8;
        int base = n0 & 255;
        float a0v[4], a1v[4], b0v[4], b1v[4];
#pragma unroll
        for (int nt = 0; nt < 4; nt++) {
            int f = head * 256 + base + wn * 32 + nt * 8 + 2 * t;
            a0v[nt] = asrc[f];  a1v[nt] = asrc[f + 1];
            b0v[nt] = adst[f];  b1v[nt] = adst[f + 1];
        }
#pragma unroll
        for (int mt = 0; mt < 4; mt++) {
            int gm = m0 + wm * 64 + mt * 16 + g;
            float s0 = 0.f, s1 = 0.f, d0 = 0.f, d1 = 0.f;
#pragma unroll
            for (int nt = 0; nt < 4; nt++) {
                int gn = n0 + wn * 32 + nt * 8 + 2 * t;
                if (mode == 0) {
                    if (gm < M)
                        *reinterpret_cast<__half2*>(C16 + (size_t)gm * ldc + gn) =
                            __floats2half2_rn(acc[mt][nt][0], acc[mt][nt][1]);
                    if (gm + 8 < M)
                        *reinterpret_cast<__half2*>(C16 + (size_t)(gm + 8) * ldc + gn) =
                            __floats2half2_rn(acc[mt][nt][2], acc[mt][nt][3]);
                } else {
                    float* p0 = C + (size_t)gm * ldc + gn;
                    if (gm < M)
                        *reinterpret_cast<float2*>(p0) =
                            make_float2(acc[mt][nt][0], acc[mt][nt][1]);
                    if (gm + 8 < M)
                        *reinterpret_cast<float2*>(p0 + 8 * ldc) =
                            make_float2(acc[mt][nt][2], acc[mt][nt][3]);
                }
                s0 += acc[mt][nt][0] * a0v[nt] + acc[mt][nt][1] * a1v[nt];
                s1 += acc[mt][nt][2] * a0v[nt] + acc[mt][nt][3] * a1v[nt];
                d0 += acc[mt][nt][0] * b0v[nt] + acc[mt][nt][1] * b1v[nt];
                d1 += acc[mt][nt][2] * b0v[nt] + acc[mt][nt][3] * b1v[nt];
            }
#pragma unroll
            for (int o = 1; o <= 2; o <<= 1) {
                s0 += __shfl_xor_sync(0xffffffffu, s0, o);
                s1 += __shfl_xor_sync(0xffffffffu, s1, o);
                d0 += __shfl_xor_sync(0xffffffffu, d0, o);
                d1 += __shfl_xor_sync(0xffffffffu, d1, o);
            }
            if (t == 0) {
                if (gm < M) {
                    atomicAdd(&pals[gm * H_ + head], s0);
                    atomicAdd(&pald[gm * H_ + head], d0);
                }
                if (gm + 8 < M) {
                    atomicAdd(&pals[(gm + 8) * H_ + head], s1);
                    atomicAdd(&pald[(gm + 8) * H_ + head], d1);
                }
            }
        }
    } else {
        bool mirror = (bx != by);
#pragma unroll
        for (int mt = 0; mt < 4; mt++) {
            int gm = m0 + wm * 64 + mt * 16 + g;
#pragma unroll
            for (int nt = 0; nt < 4; nt++) {
                int gn = n0 + wn * 32 + nt * 8 + 2 * t;
                if (gn >= Ncols) continue;
                float* p0 = C + (size_t)gm * ldc + gn;
                float s0 = 1.f / (1.f + __expf(-acc[mt][nt][0]));
                float s1 = 1.f / (1.f + __expf(-acc[mt][nt][1]));
                float s2 = 1.f / (1.f + __expf(-acc[mt][nt][2]));
                float s3 = 1.f / (1.f + __expf(-acc[mt][nt][3]));
                if (gm < M)
                    __stcs(reinterpret_cast<float2*>(p0), make_float2(s0, s1));
                if (gm + 8 < M)
                    __stcs(reinterpret_cast<float2*>(p0 + 8 * ldc), make_float2(s2, s3));
                if (mirror) {
                    float* q0 = C + (size_t)gn * ldc;
                    float* q1 = C + (size_t)(gn + 1) * ldc;
                    if (gm < M)     { __stcs(q0 + gm, s0);     __stcs(q1 + gm, s1); }
                    if (gm + 8 < M) { __stcs(q0 + gm + 8, s2); __stcs(q1 + gm + 8, s3); }
                }
            }
        }
    }
}

// ---------------- all 4 W transposes + hi/lo splits --------------------------
__global__ void wt_split_all(const float* __restrict__ W0, const float* __restrict__ W1,
                             const float* __restrict__ W2, const float* __restrict__ W3) {
    __shared__ float tbuf[32][33];
    const float* Ws[4] = { W0, W1, W2, W3 };
    int l = blockIdx.z;
    const float* W = Ws[l];
    size_t lofs = (size_t)l * HF_ * F_;
    int bx = blockIdx.x, by = blockIdx.y;
    int x = threadIdx.x, y = threadIdx.y;
    for (int i = y; i < 32; i += 8)
        tbuf[i][x] = W[(size_t)(by * 32 + i) * HF_ + bx * 32 + x];
    __syncthreads();
    for (int i = y; i < 32; i += 8) {
        float v = tbuf[x][i];
        __nv_bfloat16 h = __float2bfloat16(v);
        size_t o = lofs + (size_t)(bx * 32 + i) * F_ + by * 32 + x;
        g_wth[o] = h;
        g_wtl[o] = __float2bfloat16(v - __bfloat162float(h));
    }
}

// ---------------- x -> bf16 hi/lo + zero CSR/attn ----------------------------
__global__ void split_x(const float* __restrict__ x) {
    int i = blockIdx.x * blockDim.x + threadIdx.x;
    if (i < NN_) { g_cnt[i] = 0; g_wpos[i] = 0; }
    if (i < 2 * NN_ * H_) { g_als[i] = 0.f; g_ald[i] = 0.f; }
    if (i >= NN_ * F_) return;
    float v = x[i];
    __nv_bfloat16 h = __float2bfloat16(v);
    g_bfh[i] = h;
    g_bfl[i] = __float2bfloat16(v - __bfloat162float(h));
}

// ---------------- per-dst online softmax + aggregation ----------------------
__device__ __forceinline__ float leaky(float x) {
    return x > 0.f ? x : LEAKY * x;
}

__global__ __launch_bounds__(256) void aggregate(
    const float* __restrict__ bias, float* __restrict__ zout,
    const float* __restrict__ rals, const float* __restrict__ rald,
    float* __restrict__ zals, float* __restrict__ zald, int mode)
{
    __shared__ float swm[8][H_], sws[8][H_];
    __shared__ float s_m[H_], s_inv[H_];
    __shared__ float alpha_sh[CH][H_];
    __shared__ int   src_sh[CH];

    int n = blockIdx.x, tid = threadIdx.x;
    int wid = tid >> 5, lane = tid & 31;
    int beg = g_off[n];
    int deg = g_off[n + 1] - beg;

    if (zals != nullptr && tid < H_) {
        zals[n * H_ + tid] = 0.f;
        zald[n * H_ + tid] = 0.f;
    }

    float ald[H_];
    {
        float4 av = *reinterpret_cast<const float4*>(rald + n * H_);
        ald[0] = av.x; ald[1] = av.y; ald[2] = av.z; ald[3] = av.w;
    }

    float m[H_], s[H_];
#pragma unroll
    for (int h = 0; h < H_; h++) { m[h] = -1e30f; s[h] = 0.f; }
    for (int i = tid; i < deg; i += 256) {
        int sc = g_srcs[beg + i];
        float4 sv = *reinterpret_cast<const float4*>(rals + sc * H_);
        float ev[H_] = { leaky(sv.x + ald[0]), leaky(sv.y + ald[1]),
                         leaky(sv.z + ald[2]), leaky(sv.w + ald[3]) };
#pragma unroll
        for (int h = 0; h < H_; h++) {
            float e = ev[h];
            if (e > m[h]) { s[h] = s[h] * __expf(m[h] - e) + 1.f; m[h] = e; }
            else          s[h] += __expf(e - m[h]);
        }
    }
#pragma unroll
    for (int o = 16; o; o >>= 1) {
#pragma unroll
        for (int h = 0; h < H_; h++) {
            float mo = __shfl_down_sync(0xffffffffu, m[h], o);
            float so = __shfl_down_sync(0xffffffffu, s[h], o);
            float mn = fmaxf(m[h], mo);
            s[h] = s[h] * __expf(m[h] - mn) + so * __expf(mo - mn);
            m[h] = mn;
        }
    }
    if (lane == 0)
#pragma unroll
        for (int h = 0; h < H_; h++) { swm[wid][h] = m[h]; sws[wid][h] = s[h]; }
    __syncthreads();
    if (tid < 32) {
        bool v = lane < 8;
#pragma unroll
        for (int h = 0; h < H_; h++) {
            m[h] = v ? swm[lane][h] : -1e30f;
            s[h] = v ? sws[lane][h] : 0.f;
        }
#pragma unroll
        for (int o = 4; o; o >>= 1) {
#pragma unroll
            for (int h = 0; h < H_; h++) {
                float mo = __shfl_down_sync(0xffffffffu, m[h], o);
                float so = __shfl_down_sync(0xffffffffu, s[h], o);
                float mn = fmaxf(m[h], mo);
                s[h] = s[h] * __expf(m[h] - mn) + so * __expf(mo - mn);
                m[h] = mn;
            }
        }
        if (lane == 0)
#pragma unroll
            for (int h = 0; h < H_; h++) {
                s_m[h]   = m[h];
                s_inv[h] = 1.f / (s[h] + 1e-16f);
            }
    }
    __syncthreads();

    float sm_r[H_], si_r[H_];
#pragma unroll
    for (int h = 0; h < H_; h++) { sm_r[h] = s_m[h]; si_r[h] = s_inv[h]; }

    float acc[H_] = {0.f, 0.f, 0.f, 0.f};
    for (int base = 0; base < deg; base += CH) {
        int c = min(CH, deg - base);
        __syncthreads();
        for (int i = tid; i < c; i += 256) {
            int sc = g_srcs[beg + base + i];
            src_sh[i] = sc;
            float4 sv = *reinterpret_cast<const float4*>(rals + sc * H_);
            float ev[H_] = { leaky(sv.x + ald[0]), leaky(sv.y + ald[1]),
                             leaky(sv.z + ald[2]), leaky(sv.w + ald[3]) };
#pragma unroll
            for (int h = 0; h < H_; h++)
                alpha_sh[i][h] = __expf(ev[h] - sm_r[h]) * si_r[h];
        }
        __syncthreads();
        if (mode == 0) {
            int j = 0;
            for (; j + 4 <= c; j += 4) {
                int s0 = src_sh[j],     s1 = src_sh[j + 1];
                int s2 = src_sh[j + 2], s3 = src_sh[j + 3];
                const __half* h0 = &g_h16[(size_t)s0 * HF_ + tid];
                const __half* h1 = &g_h16[(size_t)s1 * HF_ + tid];
                const __half* h2 = &g_h16[(size_t)s2 * HF_ + tid];
                const __half* h3 = &g_h16[(size_t)s3 * HF_ + tid];
#pragma unroll
                for (int h = 0; h < H_; h++) {
                    acc[h] += alpha_sh[j][h]     * __half2float(h0[h * F_])
                            + alpha_sh[j + 1][h] * __half2float(h1[h * F_])
                            + alpha_sh[j + 2][h] * __half2float(h2[h * F_])
                            + alpha_sh[j + 3][h] * __half2float(h3[h * F_]);
                }
            }
            for (; j < c; j++) {
                int s0 = src_sh[j];
                const __half* h0 = &g_h16[(size_t)s0 * HF_ + tid];
#pragma unroll
                for (int h = 0; h < H_; h++)
                    acc[h] += alpha_sh[j][h] * __half2float(h0[h * F_]);
            }
        } else {
            int j = 0;
            for (; j + 4 <= c; j += 4) {
                int s0 = src_sh[j],     s1 = src_sh[j + 1];
                int s2 = src_sh[j + 2], s3 = src_sh[j + 3];
                const float* h0 = &g_h[(size_t)s0 * HF_ + tid];
                const float* h1 = &g_h[(size_t)s1 * HF_ + tid];
                const float* h2 = &g_h[(size_t)s2 * HF_ + tid];
                const float* h3 = &g_h[(size_t)s3 * HF_ + tid];
#pragma unroll
                for (int h = 0; h < H_; h++) {
                    acc[h] += alpha_sh[j][h]     * h0[h * F_]
                            + alpha_sh[j + 1][h] * h1[h * F_]
                            + alpha_sh[j + 2][h] * h2[h * F_]
                            + alpha_sh[j + 3][h] * h3[h * F_];
                }
            }
            for (; j < c; j++) {
                int s0 = src_sh[j];
                const float* h0 = &g_h[(size_t)s0 * HF_ + tid];
#pragma unroll
                for (int h = 0; h < H_; h++)
                    acc[h] += alpha_sh[j][h] * h0[h * F_];
            }
        }
    }

    float v = (acc[0] + acc[1] + acc[2] + acc[3]) * 0.25f + bias[tid];
    v = mode ? tanhf(v) : fmaxf(v, 0.f);
    size_t o = (size_t)n * F_ + tid;
    if (mode) zout[o] = v;
    __nv_bfloat16 hh = __float2bfloat16(v);
    g_bfh[o] = hh;
    g_bfl[o] = __float2bfloat16(v - __bfloat162float(hh));
}

// ---------------- driver ----------------------------------------------------
extern "C" void kernel_launch(void* const* d_in, const int* in_sizes, int n_in,
                              void* d_out, int out_size)
{
    const float* x  = (const float*)d_in[0];
    const int*   ei = (const int*)d_in[1];
    const float* W[4];  const float* as_[4]; const float* ad_[4]; const float* b_[4];
    for (int l = 0; l < 4; l++) {
        W[l]   = (const float*)d_in[2 + 4 * l];
        as_[l] = (const float*)d_in[3 + 4 * l];
        ad_[l] = (const float*)d_in[4 + 4 * l];
        b_[l]  = (const float*)d_in[5 + 4 * l];
    }
    float* out = (float*)d_out;

    float *p_h, *p_z, *p_als, *p_ald;
    __half* p_h16;
    __nv_bfloat16 *p_bfh, *p_bfl, *p_wth, *p_wtl;
    cudaGetSymbolAddress((void**)&p_h,    g_h);
    cudaGetSymbolAddress((void**)&p_h16,  g_h16);
    cudaGetSymbolAddress((void**)&p_z,    g_zbuf);
    cudaGetSymbolAddress((void**)&p_als,  g_als);
    cudaGetSymbolAddress((void**)&p_ald,  g_ald);
    cudaGetSymbolAddress((void**)&p_bfh,  g_bfh);
    cudaGetSymbolAddress((void**)&p_bfl,  g_bfl);
    cudaGetSymbolAddress((void**)&p_wth,  g_wth);
    cudaGetSymbolAddress((void**)&p_wtl,  g_wtl);

    const size_t ADJ = (size_t)NN_ * NN_;
    bool z_in_out = ((size_t)out_size >= ADJ + (size_t)NN_ * F_);
    float* zptr = z_in_out ? (out + ADJ) : p_z;

    static bool smem_attr = false;
    if (!smem_attr) {
        cudaFuncSetAttribute(hmma_tt, cudaFuncAttributeMaxDynamicSharedMemorySize,
                             NSTAGE * GBUF);
        smem_attr = true;
    }

    dim3 lgrid(HF_ / 128, (NN_ + 127) / 128);
    const int BUF = NN_ * H_;
    const size_t WOF = (size_t)HF_ * F_;

    // ---- prologue ----
    split_x<<<(NN_ * F_ + 255) / 256, 256>>>(x);
    wt_split_all<<<dim3(32, 8, 4), dim3(32, 8)>>>(W[0], W[1], W[2], W[3]);

    // ---- layer 0 GEMM ----
    hmma_tt<<<lgrid, 256, NSTAGE * GBUF>>>(
        p_bfh, p_bfl, p_wth, p_wtl, as_[0], ad_[0],
        p_als, p_ald, nullptr, p_h16, NN_, HF_, HF_, 0);

    // ---- CSR build ----
    count_kernel<<<(ETOT + 255) / 256, 256>>>(ei);
    scan_kernel<<<1, 1024>>>();
    scatter_kernel<<<(ETOT + 255) / 256, 256>>>(ei);

    aggregate<<<NN_, 256>>>(b_[0], nullptr, p_als, p_ald,
                            p_als + BUF, p_ald + BUF, 0);

    for (int l = 1; l < 4; l++) {
        int rb = (l & 1) * BUF;
        int zb = ((l + 1) & 1) * BUF;
        int md = (l == 3) ? 1 : 0;
        hmma_tt<<<lgrid, 256, NSTAGE * GBUF>>>(
            p_bfh, p_bfl, p_wth + (size_t)l * WOF, p_wtl + (size_t)l * WOF,
            as_[l], ad_[l], p_als + rb, p_ald + rb,
            md ? p_h : nullptr, p_h16, NN_, HF_, HF_, md);
        aggregate<<<NN_, 256>>>(b_[l], md ? zptr : nullptr,
                                p_als + rb, p_ald + rb,
                                (l < 3) ? p_als + zb : nullptr,
                                (l < 3) ? p_ald + zb : nullptr, md);
    }

    // ---- adj_recon = sigmoid(z @ z^T) ----
    hmma_tt<<<TRI, 256, NSTAGE * GBUF>>>(p_bfh, p_bfl, p_bfh, p_bfl,
                                         nullptr, nullptr, nullptr, nullptr,
                                         out, nullptr, NN_, NN_, NN_, 2);
}

// round 16
// speedup vs baseline: 1.0025x; 1.0025x over previous
#include <cuda_runtime.h>
#include <cuda_bf16.h>
#include <cuda_fp16.h>
#include <math.h>
#include <stdint.h>

#define NN_   10000
#define EE_   320000
#define ETOT  (EE_ + NN_)
#define H_    4
#define F_    256
#define HF_   1024
#define LEAKY 0.2f
#define CH    128
#define NTILE 79
#define TRI   (NTILE * (NTILE + 1) / 2)

// ---------------- scratch (device globals) ----------------------------------
__device__ float  g_h[(size_t)NN_ * HF_];          // fp32 h (layer 3)
__device__ __half g_h16[(size_t)NN_ * HF_];        // fp16 h (layers 0-2)
__device__ float  g_als[2 * NN_ * H_];             // double-buffered attn logits
__device__ float  g_ald[2 * NN_ * H_];
__device__ float  g_zbuf[(size_t)NN_ * F_];
__device__ int    g_cnt[NN_];
__device__ int    g_off[NN_ + 1];
__device__ int    g_wpos[NN_];
__device__ int    g_srcs[ETOT];
__device__ __align__(16) __nv_bfloat16 g_bfh[(size_t)NN_ * F_];
__device__ __align__(16) __nv_bfloat16 g_bfl[(size_t)NN_ * F_];
__device__ __align__(16) __nv_bfloat16 g_wth[4 * (size_t)HF_ * F_];
__device__ __align__(16) __nv_bfloat16 g_wtl[4 * (size_t)HF_ * F_];

// ---------------- small PTX helpers -----------------------------------------
__device__ __forceinline__ uint32_t smem_u32(const void* p) {
    uint32_t a;
    asm("{ .reg .u64 t; cvta.to.shared.u64 t, %1; cvt.u32.u64 %0, t; }" : "=r"(a) : "l"(p));
    return a;
}
__device__ __forceinline__ void cp16(uint32_t dst, const void* src, bool valid) {
    int sz = valid ? 16 : 0;
    asm volatile("cp.async.cg.shared.global [%0], [%1], 16, %2;"
                 :: "r"(dst), "l"(src), "r"(sz) : "memory");
}
__device__ __forceinline__ void cp_commit() {
    asm volatile("cp.async.commit_group;" ::: "memory");
}
__device__ __forceinline__ void cp_wait1() {
    asm volatile("cp.async.wait_group 1;" ::: "memory");
}
__device__ __forceinline__ void ldsm4(uint32_t& r0, uint32_t& r1, uint32_t& r2,
                                      uint32_t& r3, uint32_t a) {
    asm volatile("ldmatrix.sync.aligned.m8n8.x4.shared.b16 {%0,%1,%2,%3}, [%4];"
                 : "=r"(r0), "=r"(r1), "=r"(r2), "=r"(r3) : "r"(a));
}
__device__ __forceinline__ void mma16816(float c[4], uint32_t a0, uint32_t a1,
                                         uint32_t a2, uint32_t a3,
                                         uint32_t b0, uint32_t b1) {
    asm volatile(
        "mma.sync.aligned.m16n8k16.row.col.f32.bf16.bf16.f32 "
        "{%0,%1,%2,%3}, {%4,%5,%6,%7}, {%8,%9}, {%0,%1,%2,%3};"
        : "+f"(c[0]), "+f"(c[1]), "+f"(c[2]), "+f"(c[3])
        : "r"(a0), "r"(a1), "r"(a2), "r"(a3), "r"(b0), "r"(b1));
}

// ---------------- CSR build -------------------------------------------------
__global__ void count_kernel(const int* __restrict__ ei) {
    int e = blockIdx.x * blockDim.x + threadIdx.x;
    if (e >= ETOT) return;
    int dst = (e < EE_) ? ei[EE_ + e] : (e - EE_);
    atomicAdd(&g_cnt[dst], 1);
}
__global__ void scan_kernel() {
    __shared__ int sh[1024];
    int tid = threadIdx.x;
    int carry = 0;
    for (int base = 0; base < NN_; base += 1024) {
        int v = (base + tid < NN_) ? g_cnt[base + tid] : 0;
        sh[tid] = v;
        __syncthreads();
        for (int d = 1; d < 1024; d <<= 1) {
            int t = (tid >= d) ? sh[tid - d] : 0;
            __syncthreads();
            sh[tid] += t;
            __syncthreads();
        }
        if (base + tid < NN_) g_off[base + tid] = carry + sh[tid] - v;
        int tot = sh[1023];
        __syncthreads();
        carry += tot;
    }
    if (tid == 0) g_off[NN_] = carry;
}
__global__ void scatter_kernel(const int* __restrict__ ei) {
    int e = blockIdx.x * blockDim.x + threadIdx.x;
    if (e >= ETOT) return;
    int src, dst;
    if (e < EE_) { src = ei[e]; dst = ei[EE_ + e]; }
    else         { src = e - EE_; dst = e - EE_; }
    int pos = g_off[dst] + atomicAdd(&g_wpos[dst], 1);
    g_srcs[pos] = src;
}

// ---------------- unified bf16-split HMMA GEMM ------------------------------
// mode 0: layer GEMM, fused attn logits, h stored fp16 (C16)
// mode 1: layer GEMM, fused attn logits, h stored fp32 (C)
// mode 2: adj sigmoid, triangular grid + mirror
#define GBUF   32768
#define NSTAGE 3

__global__ __launch_bounds__(256) void hmma_tt(
    const __nv_bfloat16* __restrict__ Ah, const __nv_bfloat16* __restrict__ Al,
    const __nv_bfloat16* __restrict__ Bh, const __nv_bfloat16* __restrict__ Bl,
    const float* __restrict__ asrc, const float* __restrict__ adst,
    float* __restrict__ pals, float* __restrict__ pald,
    float* __restrict__ C, __half* __restrict__ C16,
    int M, int Ncols, size_t ldc, int mode)
{
    extern __shared__ char dyn_smem[];
    uint32_t smem_base = smem_u32(dyn_smem);

    int tid = threadIdx.x;
    int wid = tid >> 5, lane = tid & 31;
    int wm = wid >> 2, wn = wid & 3;
    int g = lane >> 2, t = lane & 3;

    int bx, by;
    if (mode == 2) {
        int j = blockIdx.x;
        bx = (int)((sqrtf(8.f * j + 1.f) - 1.f) * 0.5f);
        while ((bx + 1) * (bx + 2) / 2 <= j) bx++;
        while (bx * (bx + 1) / 2 > j) bx--;
        by = j - bx * (bx + 1) / 2;
    } else {
        bx = blockIdx.x; by = blockIdx.y;
    }
    int m0 = by * 128, n0 = bx * 128;

    const __nv_bfloat16* segA[3] = { Ah, Ah, Al };
    const __nv_bfloat16* segB[3] = { Bh, Bl, Bh };

    uint32_t l_off[4];
    size_t   l_arow[4], l_brow[4];
    bool     l_va[4], l_vb[4];
#pragma unroll
    for (int i = 0; i < 4; i++) {
        int idx = tid + i * 256;
        int r = idx >> 3, s16 = idx & 7;
        l_off[i] = (uint32_t)(r * 128 + ((s16 ^ (r & 7)) << 4));
        int gm = m0 + r, gn = n0 + r;
        l_va[i] = gm < M;
        l_vb[i] = gn < Ncols;
        l_arow[i] = (size_t)(l_va[i] ? gm : 0) * (F_ * 2) + (size_t)s16 * 16;
        l_brow[i] = (size_t)(l_vb[i] ? gn : 0) * (F_ * 2) + (size_t)s16 * 16;
    }

    float acc[4][4][4];
#pragma unroll
    for (int i = 0; i < 4; i++)
#pragma unroll
        for (int j2 = 0; j2 < 4; j2++)
#pragma unroll
            for (int k = 0; k < 4; k++) acc[i][j2][k] = 0.f;

    auto issue_chunk = [&](int c) {
        int seg = c >> 2;
        size_t kb = (size_t)((c & 3) * 64) * 2;
        const char* As = (const char*)segA[seg] + kb;
        const char* Bs = (const char*)segB[seg] + kb;
        uint32_t sa = smem_base + (c % NSTAGE) * GBUF;
        uint32_t sb = sa + 16384;
#pragma unroll
        for (int i = 0; i < 4; i++) {
            cp16(sa + l_off[i], As + l_arow[i], l_va[i]);
            cp16(sb + l_off[i], Bs + l_brow[i], l_vb[i]);
        }
        cp_commit();
    };

    issue_chunk(0);
    issue_chunk(1);

    int lr = lane & 15;
    uint32_t a_rowoff[4], b_rowoff[2];
    uint32_t rxa = (uint32_t)(lr & 7) << 4, lhalf = (uint32_t)(lane >> 4) << 4;
#pragma unroll
    for (int mt = 0; mt < 4; mt++)
        a_rowoff[mt] = (uint32_t)((wm * 64 + mt * 16 + lr) * 128);
#pragma unroll
    for (int hb = 0; hb < 2; hb++)
        b_rowoff[hb] = (uint32_t)((wn * 32 + hb * 16 + lr) * 128);

    for (int c = 0; c < 12; c++) {
        cp_wait1();
        __syncthreads();
        if (c + 2 < 12) issue_chunk(c + 2);

        uint32_t sa = smem_base + (c % NSTAGE) * GBUF;
        uint32_t sb = sa + 16384;
#pragma unroll
        for (int ks = 0; ks < 4; ks++) {
            uint32_t xr = ((uint32_t)(2 * ks) << 4) + lhalf;
            uint32_t af[4][4];
#pragma unroll
            for (int mt = 0; mt < 4; mt++)
                ldsm4(af[mt][0], af[mt][1], af[mt][2], af[mt][3],
                      sa + a_rowoff[mt] + (xr ^ rxa));
            uint32_t bq[2][4];
#pragma unroll
            for (int hb = 0; hb < 2; hb++)
                ldsm4(bq[hb][0], bq[hb][1], bq[hb][2], bq[hb][3],
                      sb + b_rowoff[hb] + (xr ^ rxa));
#pragma unroll
            for (int mt = 0; mt < 4; mt++)
#pragma unroll
                for (int nt = 0; nt < 4; nt++)
                    mma16816(acc[mt][nt],
                             af[mt][0], af[mt][1], af[mt][2], af[mt][3],
                             bq[nt >> 1][nt & 1], bq[nt >> 1][(nt & 1) + 2]);
        }
    }

    if (mode <= 1) {
        int head = n0 >> 8;
        int base = n0 & 255;
        float a0v[4], a1v[4], b0v[4], b1v[4];
#pragma unroll
        for (int nt = 0; nt < 4; nt++) {
            int f = head * 256 + base + wn * 32 + nt * 8 + 2 * t;
            a0v[nt] = asrc[f];  a1v[nt] = asrc[f + 1];
            b0v[nt] = adst[f];  b1v[nt] = adst[f + 1];
        }
#pragma unroll
        for (int mt = 0; mt < 4; mt++) {
            int gm = m0 + wm * 64 + mt * 16 + g;
            float s0 = 0.f, s1 = 0.f, d0 = 0.f, d1 = 0.f;
#pragma unroll
            for (int nt = 0; nt < 4; nt++) {
                int gn = n0 + wn * 32 + nt * 8 + 2 * t;
                if (mode == 0) {
                    if (gm < M)
                        *reinterpret_cast<__half2*>(C16 + (size_t)gm * ldc + gn) =
                            __floats2half2_rn(acc[mt][nt][0], acc[mt][nt][1]);
                    if (gm + 8 < M)
                        *reinterpret_cast<__half2*>(C16 + (size_t)(gm + 8) * ldc + gn) =
                            __floats2half2_rn(acc[mt][nt][2], acc[mt][nt][3]);
                } else {
                    float* p0 = C + (size_t)gm * ldc + gn;
                    if (gm < M)
                        *reinterpret_cast<float2*>(p0) =
                            make_float2(acc[mt][nt][0], acc[mt][nt][1]);
                    if (gm + 8 < M)
                        *reinterpret_cast<float2*>(p0 + 8 * ldc) =
                            make_float2(acc[mt][nt][2], acc[mt][nt][3]);
                }
                s0 += acc[mt][nt][0] * a0v[nt] + acc[mt][nt][1] * a1v[nt];
                s1 += acc[mt][nt][2] * a0v[nt] + acc[mt][nt][3] * a1v[nt];
                d0 += acc[mt][nt][0] * b0v[nt] + acc[mt][nt][1] * b1v[nt];
                d1 += acc[mt][nt][2] * b0v[nt] + acc[mt][nt][3] * b1v[nt];
            }
#pragma unroll
            for (int o = 1; o <= 2; o <<= 1) {
                s0 += __shfl_xor_sync(0xffffffffu, s0, o);
                s1 += __shfl_xor_sync(0xffffffffu, s1, o);
                d0 += __shfl_xor_sync(0xffffffffu, d0, o);
                d1 += __shfl_xor_sync(0xffffffffu, d1, o);
            }
            if (t == 0) {
                if (gm < M) {
                    atomicAdd(&pals[gm * H_ + head], s0);
                    atomicAdd(&pald[gm * H_ + head], d0);
                }
                if (gm + 8 < M) {
                    atomicAdd(&pals[(gm + 8) * H_ + head], s1);
                    atomicAdd(&pald[(gm + 8) * H_ + head], d1);
                }
            }
        }
    } else {
        bool mirror = (bx != by);
#pragma unroll
        for (int mt = 0; mt < 4; mt++) {
            int gm = m0 + wm * 64 + mt * 16 + g;
#pragma unroll
            for (int nt = 0; nt < 4; nt++) {
                int gn = n0 + wn * 32 + nt * 8 + 2 * t;
                if (gn >= Ncols) continue;
                float* p0 = C + (size_t)gm * ldc + gn;
                float s0 = 1.f / (1.f + __expf(-acc[mt][nt][0]));
                float s1 = 1.f / (1.f + __expf(-acc[mt][nt][1]));
                float s2 = 1.f / (1.f + __expf(-acc[mt][nt][2]));
                float s3 = 1.f / (1.f + __expf(-acc[mt][nt][3]));
                if (gm < M)
                    __stcs(reinterpret_cast<float2*>(p0), make_float2(s0, s1));
                if (gm + 8 < M)
                    __stcs(reinterpret_cast<float2*>(p0 + 8 * ldc), make_float2(s2, s3));
                if (mirror) {
                    float* q0 = C + (size_t)gn * ldc;
                    float* q1 = C + (size_t)(gn + 1) * ldc;
                    if (gm < M)     { __stcs(q0 + gm, s0);     __stcs(q1 + gm, s1); }
                    if (gm + 8 < M) { __stcs(q0 + gm + 8, s2); __stcs(q1 + gm + 8, s3); }
                }
            }
        }
    }
}

// ---------------- all 4 W transposes + hi/lo splits --------------------------
__global__ void wt_split_all(const float* __restrict__ W0, const float* __restrict__ W1,
                             const float* __restrict__ W2, const float* __restrict__ W3) {
    __shared__ float tbuf[32][33];
    const float* Ws[4] = { W0, W1, W2, W3 };
    int l = blockIdx.z;
    const float* W = Ws[l];
    size_t lofs = (size_t)l * HF_ * F_;
    int bx = blockIdx.x, by = blockIdx.y;
    int x = threadIdx.x, y = threadIdx.y;
    for (int i = y; i < 32; i += 8)
        tbuf[i][x] = W[(size_t)(by * 32 + i) * HF_ + bx * 32 + x];
    __syncthreads();
    for (int i = y; i < 32; i += 8) {
        float v = tbuf[x][i];
        __nv_bfloat16 h = __float2bfloat16(v);
        size_t o = lofs + (size_t)(bx * 32 + i) * F_ + by * 32 + x;
        g_wth[o] = h;
        g_wtl[o] = __float2bfloat16(v - __bfloat162float(h));
    }
}

// ---------------- x -> bf16 hi/lo + zero CSR/attn ----------------------------
__global__ void split_x(const float* __restrict__ x) {
    int i = blockIdx.x * blockDim.x + threadIdx.x;
    if (i < NN_) { g_cnt[i] = 0; g_wpos[i] = 0; }
    if (i < 2 * NN_ * H_) { g_als[i] = 0.f; g_ald[i] = 0.f; }
    if (i >= NN_ * F_) return;
    float v = x[i];
    __nv_bfloat16 h = __float2bfloat16(v);
    g_bfh[i] = h;
    g_bfl[i] = __float2bfloat16(v - __bfloat162float(h));
}

// ---------------- per-dst online softmax + aggregation ----------------------
// mode 0: fp16 h gather, relu, no z output. mode 1: fp32 h gather, tanh, z out.
__device__ __forceinline__ float leaky(float x) {
    return x > 0.f ? x : LEAKY * x;
}

__global__ __launch_bounds__(256) void aggregate(
    const float* __restrict__ bias, float* __restrict__ zout,
    const float* __restrict__ rals, const float* __restrict__ rald,
    float* __restrict__ zals, float* __restrict__ zald, int mode)
{
    __shared__ float swm[8][H_], sws[8][H_];
    __shared__ float s_m[H_], s_inv[H_];
    __shared__ float alpha_sh[CH][H_];
    __shared__ int   src_sh[CH];

    int n = blockIdx.x, tid = threadIdx.x;
    int wid = tid >> 5, lane = tid & 31;
    int beg = g_off[n];
    int deg = g_off[n + 1] - beg;

    // zero the NEXT layer's attn accumulator entries for this node
    if (zals != nullptr && tid < H_) {
        zals[n * H_ + tid] = 0.f;
        zald[n * H_ + tid] = 0.f;
    }

    float ald[H_];
#pragma unroll
    for (int h = 0; h < H_; h++) ald[h] = rald[n * H_ + h];

    float m[H_], s[H_];
#pragma unroll
    for (int h = 0; h < H_; h++) { m[h] = -1e30f; s[h] = 0.f; }
    for (int i = tid; i < deg; i += 256) {
        int sc = g_srcs[beg + i];
#pragma unroll
        for (int h = 0; h < H_; h++) {
            float e = leaky(rals[sc * H_ + h] + ald[h]);
            if (e > m[h]) { s[h] = s[h] * __expf(m[h] - e) + 1.f; m[h] = e; }
            else          s[h] += __expf(e - m[h]);
        }
    }
#pragma unroll
    for (int o = 16; o; o >>= 1) {
#pragma unroll
        for (int h = 0; h < H_; h++) {
            float mo = __shfl_down_sync(0xffffffffu, m[h], o);
            float so = __shfl_down_sync(0xffffffffu, s[h], o);
            float mn = fmaxf(m[h], mo);
            s[h] = s[h] * __expf(m[h] - mn) + so * __expf(mo - mn);
            m[h] = mn;
        }
    }
    if (lane == 0)
#pragma unroll
        for (int h = 0; h < H_; h++) { swm[wid][h] = m[h]; sws[wid][h] = s[h]; }
    __syncthreads();
    if (tid < 32) {
        bool v = lane < 8;
#pragma unroll
        for (int h = 0; h < H_; h++) {
            m[h] = v ? swm[lane][h] : -1e30f;
            s[h] = v ? sws[lane][h] : 0.f;
        }
#pragma unroll
        for (int o = 4; o; o >>= 1) {
#pragma unroll
            for (int h = 0; h < H_; h++) {
                float mo = __shfl_down_sync(0xffffffffu, m[h], o);
                float so = __shfl_down_sync(0xffffffffu, s[h], o);
                float mn = fmaxf(m[h], mo);
                s[h] = s[h] * __expf(m[h] - mn) + so * __expf(mo - mn);
                m[h] = mn;
            }
        }
        if (lane == 0)
#pragma unroll
            for (int h = 0; h < H_; h++) {
                s_m[h]   = m[h];
                s_inv[h] = 1.f / (s[h] + 1e-16f);
            }
    }
    __syncthreads();

    float sm_r[H_], si_r[H_];
#pragma unroll
    for (int h = 0; h < H_; h++) { sm_r[h] = s_m[h]; si_r[h] = s_inv[h]; }

    float acc[H_] = {0.f, 0.f, 0.f, 0.f};
    for (int base = 0; base < deg; base += CH) {
        int c = min(CH, deg - base);
        __syncthreads();
        for (int i = tid; i < c; i += 256) {
            int sc = g_srcs[beg + base + i];
            src_sh[i] = sc;
#pragma unroll
            for (int h = 0; h < H_; h++) {
                float e = leaky(rals[sc * H_ + h] + ald[h]);
                alpha_sh[i][h] = __expf(e - sm_r[h]) * si_r[h];
            }
        }
        __syncthreads();
        if (mode == 0) {
            int j = 0;
            for (; j + 4 <= c; j += 4) {
                int s0 = src_sh[j],     s1 = src_sh[j + 1];
                int s2 = src_sh[j + 2], s3 = src_sh[j + 3];
                const __half* h0 = &g_h16[(size_t)s0 * HF_ + tid];
                const __half* h1 = &g_h16[(size_t)s1 * HF_ + tid];
                const __half* h2 = &g_h16[(size_t)s2 * HF_ + tid];
                const __half* h3 = &g_h16[(size_t)s3 * HF_ + tid];
#pragma unroll
                for (int h = 0; h < H_; h++) {
                    acc[h] += alpha_sh[j][h]     * __half2float(h0[h * F_])
                            + alpha_sh[j + 1][h] * __half2float(h1[h * F_])
                            + alpha_sh[j + 2][h] * __half2float(h2[h * F_])
                            + alpha_sh[j + 3][h] * __half2float(h3[h * F_]);
                }
            }
            for (; j < c; j++) {
                int s0 = src_sh[j];
                const __half* h0 = &g_h16[(size_t)s0 * HF_ + tid];
#pragma unroll
                for (int h = 0; h < H_; h++)
                    acc[h] += alpha_sh[j][h] * __half2float(h0[h * F_]);
            }
        } else {
            int j = 0;
            for (; j + 4 <= c; j += 4) {
                int s0 = src_sh[j],     s1 = src_sh[j + 1];
                int s2 = src_sh[j + 2], s3 = src_sh[j + 3];
                const float* h0 = &g_h[(size_t)s0 * HF_ + tid];
                const float* h1 = &g_h[(size_t)s1 * HF_ + tid];
                const float* h2 = &g_h[(size_t)s2 * HF_ + tid];
                const float* h3 = &g_h[(size_t)s3 * HF_ + tid];
#pragma unroll
                for (int h = 0; h < H_; h++) {
                    acc[h] += alpha_sh[j][h]     * h0[h * F_]
                            + alpha_sh[j + 1][h] * h1[h * F_]
                            + alpha_sh[j + 2][h] * h2[h * F_]
                            + alpha_sh[j + 3][h] * h3[h * F_];
                }
            }
            for (; j < c; j++) {
                int s0 = src_sh[j];
                const float* h0 = &g_h[(size_t)s0 * HF_ + tid];
#pragma unroll
                for (int h = 0; h < H_; h++)
                    acc[h] += alpha_sh[j][h] * h0[h * F_];
            }
        }
    }

    float v = (acc[0] + acc[1] + acc[2] + acc[3]) * 0.25f + bias[tid];
    v = mode ? tanhf(v) : fmaxf(v, 0.f);
    size_t o = (size_t)n * F_ + tid;
    if (mode) zout[o] = v;
    __nv_bfloat16 hh = __float2bfloat16(v);
    g_bfh[o] = hh;
    g_bfl[o] = __float2bfloat16(v - __bfloat162float(hh));
}

// ---------------- driver ----------------------------------------------------
extern "C" void kernel_launch(void* const* d_in, const int* in_sizes, int n_in,
                              void* d_out, int out_size)
{
    const float* x  = (const float*)d_in[0];
    const int*   ei = (const int*)d_in[1];
    const float* W[4];  const float* as_[4]; const float* ad_[4]; const float* b_[4];
    for (int l = 0; l < 4; l++) {
        W[l]   = (const float*)d_in[2 + 4 * l];
        as_[l] = (const float*)d_in[3 + 4 * l];
        ad_[l] = (const float*)d_in[4 + 4 * l];
        b_[l]  = (const float*)d_in[5 + 4 * l];
    }
    float* out = (float*)d_out;

    float *p_h, *p_z, *p_als, *p_ald;
    __half* p_h16;
    __nv_bfloat16 *p_bfh, *p_bfl, *p_wth, *p_wtl;
    cudaGetSymbolAddress((void**)&p_h,    g_h);
    cudaGetSymbolAddress((void**)&p_h16,  g_h16);
    cudaGetSymbolAddress((void**)&p_z,    g_zbuf);
    cudaGetSymbolAddress((void**)&p_als,  g_als);
    cudaGetSymbolAddress((void**)&p_ald,  g_ald);
    cudaGetSymbolAddress((void**)&p_bfh,  g_bfh);
    cudaGetSymbolAddress((void**)&p_bfl,  g_bfl);
    cudaGetSymbolAddress((void**)&p_wth,  g_wth);
    cudaGetSymbolAddress((void**)&p_wtl,  g_wtl);

    const size_t ADJ = (size_t)NN_ * NN_;
    bool z_in_out = ((size_t)out_size >= ADJ + (size_t)NN_ * F_);
    float* zptr = z_in_out ? (out + ADJ) : p_z;

    static bool smem_attr = false;
    if (!smem_attr) {
        cudaFuncSetAttribute(hmma_tt, cudaFuncAttributeMaxDynamicSharedMemorySize,
                             NSTAGE * GBUF);
        smem_attr = true;
    }

    dim3 lgrid(HF_ / 128, (NN_ + 127) / 128);
    const int BUF = NN_ * H_;
    const size_t WOF = (size_t)HF_ * F_;

    // ---- prologue: splits + zeroing, all 4 weight splits ----
    split_x<<<(NN_ * F_ + 255) / 256, 256>>>(x);
    wt_split_all<<<dim3(32, 8, 4), dim3(32, 8)>>>(W[0], W[1], W[2], W[3]);

    // ---- layer 0 GEMM ----
    hmma_tt<<<lgrid, 256, NSTAGE * GBUF>>>(
        p_bfh, p_bfl, p_wth, p_wtl, as_[0], ad_[0],
        p_als, p_ald, nullptr, p_h16, NN_, HF_, HF_, 0);

    // ---- CSR build ----
    count_kernel<<<(ETOT + 255) / 256, 256>>>(ei);
    scan_kernel<<<1, 1024>>>();
    scatter_kernel<<<(ETOT + 255) / 256, 256>>>(ei);

    // ---- A0 (reads buf0, zeroes buf1) ----
    aggregate<<<NN_, 256>>>(b_[0], nullptr, p_als, p_ald,
                            p_als + BUF, p_ald + BUF, 0);

    // ---- layers 1..3 ----
    for (int l = 1; l < 4; l++) {
        int rb = (l & 1) * BUF;
        int zb = ((l + 1) & 1) * BUF;
        int md = (l == 3) ? 1 : 0;
        hmma_tt<<<lgrid, 256, NSTAGE * GBUF>>>(
            p_bfh, p_bfl, p_wth + (size_t)l * WOF, p_wtl + (size_t)l * WOF,
            as_[l], ad_[l], p_als + rb, p_ald + rb,
            md ? p_h : nullptr, p_h16, NN_, HF_, HF_, md);
        aggregate<<<NN_, 256>>>(b_[l], md ? zptr : nullptr,
                                p_als + rb, p_ald + rb,
                                (l < 3) ? p_als + zb : nullptr,
                                (l < 3) ? p_ald + zb : nullptr, md);
    }

    // ---- adj_recon = sigmoid(z @ z^T), triangular grid + mirror ----
    hmma_tt<<<TRI, 256, NSTAGE * GBUF>>>(p_bfh, p_bfl, p_bfh, p_bfl,
                                         nullptr, nullptr, nullptr, nullptr,
                                         out, nullptr, NN_, NN_, NN_, 2);
}

// round 17
// speedup vs baseline: 1.5490x; 1.5451x over previous
#include <cuda_runtime.h>
#include <cuda_bf16.h>
#include <cuda_fp16.h>
#include <math.h>
#include <stdint.h>

#define NN_   10000
#define EE_   320000
#define ETOT  (EE_ + NN_)
#define H_    4
#define F_    256
#define HF_   1024
#define LEAKY 0.2f
#define CH    128
#define NTILE 79
#define TRI   (NTILE * (NTILE + 1) / 2)

// ---------------- scratch (device globals) ----------------------------------
__device__ float  g_h[(size_t)NN_ * HF_];          // fp32 h (layer 3)
__device__ __half g_h16[(size_t)NN_ * HF_];        // fp16 h (layers 0-2)
__device__ float  g_als[2 * NN_ * H_];             // double-buffered attn logits
__device__ float  g_ald[2 * NN_ * H_];
__device__ float  g_zbuf[(size_t)NN_ * F_];
__device__ int    g_cnt[NN_];
__device__ int    g_off[NN_ + 1];
__device__ int    g_wpos[NN_];
__device__ int    g_srcs[ETOT];
__device__ __align__(16) __nv_bfloat16 g_bfh[(size_t)NN_ * F_];
__device__ __align__(16) __nv_bfloat16 g_bfl[(size_t)NN_ * F_];
__device__ __align__(16) __nv_bfloat16 g_wth[4 * (size_t)HF_ * F_];
__device__ __align__(16) __nv_bfloat16 g_wtl[4 * (size_t)HF_ * F_];

// ---------------- small PTX helpers -----------------------------------------
__device__ __forceinline__ uint32_t smem_u32(const void* p) {
    uint32_t a;
    asm("{ .reg .u64 t; cvta.to.shared.u64 t, %1; cvt.u32.u64 %0, t; }" : "=r"(a) : "l"(p));
    return a;
}
__device__ __forceinline__ void cp16(uint32_t dst, const void* src, bool valid) {
    int sz = valid ? 16 : 0;
    asm volatile("cp.async.cg.shared.global [%0], [%1], 16, %2;"
                 :: "r"(dst), "l"(src), "r"(sz) : "memory");
}
__device__ __forceinline__ void cp_commit() {
    asm volatile("cp.async.commit_group;" ::: "memory");
}
__device__ __forceinline__ void cp_wait1() {
    asm volatile("cp.async.wait_group 1;" ::: "memory");
}
__device__ __forceinline__ void ldsm4(uint32_t& r0, uint32_t& r1, uint32_t& r2,
                                      uint32_t& r3, uint32_t a) {
    asm volatile("ldmatrix.sync.aligned.m8n8.x4.shared.b16 {%0,%1,%2,%3}, [%4];"
                 : "=r"(r0), "=r"(r1), "=r"(r2), "=r"(r3) : "r"(a));
}
__device__ __forceinline__ void mma16816(float c[4], uint32_t a0, uint32_t a1,
                                         uint32_t a2, uint32_t a3,
                                         uint32_t b0, uint32_t b1) {
    asm volatile(
        "mma.sync.aligned.m16n8k16.row.col.f32.bf16.bf16.f32 "
        "{%0,%1,%2,%3}, {%4,%5,%6,%7}, {%8,%9}, {%0,%1,%2,%3};"
        : "+f"(c[0]), "+f"(c[1]), "+f"(c[2]), "+f"(c[3])
        : "r"(a0), "r"(a1), "r"(a2), "r"(a3), "r"(b0), "r"(b1));
}

// ---------------- CSR build -------------------------------------------------
__global__ void count_kernel(const int* __restrict__ ei) {
    int e = blockIdx.x * blockDim.x + threadIdx.x;
    if (e >= ETOT) return;
    int dst = (e < EE_) ? ei[EE_ + e] : (e - EE_);
    atomicAdd(&g_cnt[dst], 1);
}
__global__ void scan_kernel() {
    __shared__ int sh[1024];
    int tid = threadIdx.x;
    int carry = 0;
    for (int base = 0; base < NN_; base += 1024) {
        int v = (base + tid < NN_) ? g_cnt[base + tid] : 0;
        sh[tid] = v;
        __syncthreads();
        for (int d = 1; d < 1024; d <<= 1) {
            int t = (tid >= d) ? sh[tid - d] : 0;
            __syncthreads();
            sh[tid] += t;
            __syncthreads();
        }
        if (base + tid < NN_) g_off[base + tid] = carry + sh[tid] - v;
        int tot = sh[1023];
        __syncthreads();
        carry += tot;
    }
    if (tid == 0) g_off[NN_] = carry;
}
__global__ void scatter_kernel(const int* __restrict__ ei) {
    int e = blockIdx.x * blockDim.x + threadIdx.x;
    if (e >= ETOT) return;
    int src, dst;
    if (e < EE_) { src = ei[e]; dst = ei[EE_ + e]; }
    else         { src = e - EE_; dst = e - EE_; }
    int pos = g_off[dst] + atomicAdd(&g_wpos[dst], 1);
    g_srcs[pos] = src;
}

// ---------------- unified bf16-split HMMA GEMM ------------------------------
// mode 0: layer GEMM, fused attn logits, h stored fp16 (C16)
// mode 1: layer GEMM, fused attn logits, h stored fp32 (C)
// mode 2: adj sigmoid, triangular grid + mirror
#define GBUF   32768
#define NSTAGE 3

__global__ __launch_bounds__(256) void hmma_tt(
    const __nv_bfloat16* __restrict__ Ah, const __nv_bfloat16* __restrict__ Al,
    const __nv_bfloat16* __restrict__ Bh, const __nv_bfloat16* __restrict__ Bl,
    const float* __restrict__ asrc, const float* __restrict__ adst,
    float* __restrict__ pals, float* __restrict__ pald,
    float* __restrict__ C, __half* __restrict__ C16,
    int M, int Ncols, size_t ldc, int mode)
{
    extern __shared__ char dyn_smem[];
    uint32_t smem_base = smem_u32(dyn_smem);

    int tid = threadIdx.x;
    int wid = tid >> 5, lane = tid & 31;
    int wm = wid >> 2, wn = wid & 3;
    int g = lane >> 2, t = lane & 3;

    int bx, by;
    if (mode == 2) {
        int j = blockIdx.x;
        bx = (int)((sqrtf(8.f * j + 1.f) - 1.f) * 0.5f);
        while ((bx + 1) * (bx + 2) / 2 <= j) bx++;
        while (bx * (bx + 1) / 2 > j) bx--;
        by = j - bx * (bx + 1) / 2;
    } else {
        bx = blockIdx.x; by = blockIdx.y;
    }
    int m0 = by * 128, n0 = bx * 128;

    const __nv_bfloat16* segA[3] = { Ah, Ah, Al };
    const __nv_bfloat16* segB[3] = { Bh, Bl, Bh };

    uint32_t l_off[4];
    size_t   l_arow[4], l_brow[4];
    bool     l_va[4], l_vb[4];
#pragma unroll
    for (int i = 0; i < 4; i++) {
        int idx = tid + i * 256;
        int r = idx >> 3, s16 = idx & 7;
        l_off[i] = (uint32_t)(r * 128 + ((s16 ^ (r & 7)) << 4));
        int gm = m0 + r, gn = n0 + r;
        l_va[i] = gm < M;
        l_vb[i] = gn < Ncols;
        l_arow[i] = (size_t)(l_va[i] ? gm : 0) * (F_ * 2) + (size_t)s16 * 16;
        l_brow[i] = (size_t)(l_vb[i] ? gn : 0) * (F_ * 2) + (size_t)s16 * 16;
    }

    float acc[4][4][4];
#pragma unroll
    for (int i = 0; i < 4; i++)
#pragma unroll
        for (int j2 = 0; j2 < 4; j2++)
#pragma unroll
            for (int k = 0; k < 4; k++) acc[i][j2][k] = 0.f;

    auto issue_chunk = [&](int c) {
        int seg = c >> 2;
        size_t kb = (size_t)((c & 3) * 64) * 2;
        const char* As = (const char*)segA[seg] + kb;
        const char* Bs = (const char*)segB[seg] + kb;
        uint32_t sa = smem_base + (c % NSTAGE) * GBUF;
        uint32_t sb = sa + 16384;
#pragma unroll
        for (int i = 0; i < 4; i++) {
            cp16(sa + l_off[i], As + l_arow[i], l_va[i]);
            cp16(sb + l_off[i], Bs + l_brow[i], l_vb[i]);
        }
        cp_commit();
    };

    issue_chunk(0);
    issue_chunk(1);

    int lr = lane & 15;
    uint32_t a_rowoff[4], b_rowoff[2];
    uint32_t rxa = (uint32_t)(lr & 7) << 4, lhalf = (uint32_t)(lane >> 4) << 4;
#pragma unroll
    for (int mt = 0; mt < 4; mt++)
        a_rowoff[mt] = (uint32_t)((wm * 64 + mt * 16 + lr) * 128);
#pragma unroll
    for (int hb = 0; hb < 2; hb++)
        b_rowoff[hb] = (uint32_t)((wn * 32 + hb * 16 + lr) * 128);

    for (int c = 0; c < 12; c++) {
        cp_wait1();
        __syncthreads();
        if (c + 2 < 12) issue_chunk(c + 2);

        uint32_t sa = smem_base + (c % NSTAGE) * GBUF;
        uint32_t sb = sa + 16384;
#pragma unroll
        for (int ks = 0; ks < 4; ks++) {
            uint32_t xr = ((uint32_t)(2 * ks) << 4) + lhalf;
            uint32_t af[4][4];
#pragma unroll
            for (int mt = 0; mt < 4; mt++)
                ldsm4(af[mt][0], af[mt][1], af[mt][2], af[mt][3],
                      sa + a_rowoff[mt] + (xr ^ rxa));
            uint32_t bq[2][4];
#pragma unroll
            for (int hb = 0; hb < 2; hb++)
                ldsm4(bq[hb][0], bq[hb][1], bq[hb][2], bq[hb][3],
                      sb + b_rowoff[hb] + (xr ^ rxa));
#pragma unroll
            for (int mt = 0; mt < 4; mt++)
#pragma unroll
                for (int nt = 0; nt < 4; nt++)
                    mma16816(acc[mt][nt],
                             af[mt][0], af[mt][1], af[mt][2], af[mt][3],
                             bq[nt >> 1][nt & 1], bq[nt >> 1][(nt & 1) + 2]);
        }
    }

    if (mode <= 1) {
        int head = n0 >> 8;
        int base = n0 & 255;
        float a0v[4], a1v[4], b0v[4], b1v[4];
#pragma unroll
        for (int nt = 0; nt < 4; nt++) {
            int f = head * 256 + base + wn * 32 + nt * 8 + 2 * t;
            a0v[nt] = asrc[f];  a1v[nt] = asrc[f + 1];
            b0v[nt] = adst[f];  b1v[nt] = adst[f + 1];
        }
#pragma unroll
        for (int mt = 0; mt < 4; mt++) {
            int gm = m0 + wm * 64 + mt * 16 + g;
            float s0 = 0.f, s1 = 0.f, d0 = 0.f, d1 = 0.f;
#pragma unroll
            for (int nt = 0; nt < 4; nt++) {
                int gn = n0 + wn * 32 + nt * 8 + 2 * t;
                if (mode == 0) {
                    if (gm < M)
                        *reinterpret_cast<__half2*>(C16 + (size_t)gm * ldc + gn) =
                            __floats2half2_rn(acc[mt][nt][0], acc[mt][nt][1]);
                    if (gm + 8 < M)
                        *reinterpret_cast<__half2*>(C16 + (size_t)(gm + 8) * ldc + gn) =
                            __floats2half2_rn(acc[mt][nt][2], acc[mt][nt][3]);
                } else {
                    float* p0 = C + (size_t)gm * ldc + gn;
                    if (gm < M)
                        *reinterpret_cast<float2*>(p0) =
                            make_float2(acc[mt][nt][0], acc[mt][nt][1]);
                    if (gm + 8 < M)
                        *reinterpret_cast<float2*>(p0 + 8 * ldc) =
                            make_float2(acc[mt][nt][2], acc[mt][nt][3]);
                }
                s0 += acc[mt][nt][0] * a0v[nt] + acc[mt][nt][1] * a1v[nt];
                s1 += acc[mt][nt][2] * a0v[nt] + acc[mt][nt][3] * a1v[nt];
                d0 += acc[mt][nt][0] * b0v[nt] + acc[mt][nt][1] * b1v[nt];
                d1 += acc[mt][nt][2] * b0v[nt] + acc[mt][nt][3] * b1v[nt];
            }
#pragma unroll
            for (int o = 1; o <= 2; o <<= 1) {
                s0 += __shfl_xor_sync(0xffffffffu, s0, o);
                s1 += __shfl_xor_sync(0xffffffffu, s1, o);
                d0 += __shfl_xor_sync(0xffffffffu, d0, o);
                d1 += __shfl_xor_sync(0xffffffffu, d1, o);
            }
            if (t == 0) {
                if (gm < M) {
                    atomicAdd(&pals[gm * H_ + head], s0);
                    atomicAdd(&pald[gm * H_ + head], d0);
                }
                if (gm + 8 < M) {
                    atomicAdd(&pals[(gm + 8) * H_ + head], s1);
                    atomicAdd(&pald[(gm + 8) * H_ + head], d1);
                }
            }
        }
    } else {
        bool mirror = (bx != by);
#pragma unroll
        for (int mt = 0; mt < 4; mt++) {
            int gm = m0 + wm * 64 + mt * 16 + g;
#pragma unroll
            for (int nt = 0; nt < 4; nt++) {
                int gn = n0 + wn * 32 + nt * 8 + 2 * t;
                if (gn >= Ncols) continue;
                float* p0 = C + (size_t)gm * ldc + gn;
                float s0 = 1.f / (1.f + __expf(-acc[mt][nt][0]));
                float s1 = 1.f / (1.f + __expf(-acc[mt][nt][1]));
                float s2 = 1.f / (1.f + __expf(-acc[mt][nt][2]));
                float s3 = 1.f / (1.f + __expf(-acc[mt][nt][3]));
                if (gm < M)
                    __stcs(reinterpret_cast<float2*>(p0), make_float2(s0, s1));
                if (gm + 8 < M)
                    __stcs(reinterpret_cast<float2*>(p0 + 8 * ldc), make_float2(s2, s3));
                if (mirror) {
                    float* q0 = C + (size_t)gn * ldc;
                    float* q1 = C + (size_t)(gn + 1) * ldc;
                    if (gm < M)     { __stcs(q0 + gm, s0);     __stcs(q1 + gm, s1); }
                    if (gm + 8 < M) { __stcs(q0 + gm + 8, s2); __stcs(q1 + gm + 8, s3); }
                }
            }
        }
    }
}

// ---------------- all 4 W transposes + hi/lo splits --------------------------
__global__ void wt_split_all(const float* __restrict__ W0, const float* __restrict__ W1,
                             const float* __restrict__ W2, const float* __restrict__ W3) {
    __shared__ float tbuf[32][33];
    const float* Ws[4] = { W0, W1, W2, W3 };
    int l = blockIdx.z;
    const float* W = Ws[l];
    size_t lofs = (size_t)l * HF_ * F_;
    int bx = blockIdx.x, by = blockIdx.y;
    int x = threadIdx.x, y = threadIdx.y;
    for (int i = y; i < 32; i += 8)
        tbuf[i][x] = W[(size_t)(by * 32 + i) * HF_ + bx * 32 + x];
    __syncthreads();
    for (int i = y; i < 32; i += 8) {
        float v = tbuf[x][i];
        __nv_bfloat16 h = __float2bfloat16(v);
        size_t o = lofs + (size_t)(bx * 32 + i) * F_ + by * 32 + x;
        g_wth[o] = h;
        g_wtl[o] = __float2bfloat16(v - __bfloat162float(h));
    }
}

// ---------------- x -> bf16 hi/lo + zero CSR/attn ----------------------------
__global__ void split_x(const float* __restrict__ x) {
    int i = blockIdx.x * blockDim.x + threadIdx.x;
    if (i < NN_) { g_cnt[i] = 0; g_wpos[i] = 0; }
    if (i < 2 * NN_ * H_) { g_als[i] = 0.f; g_ald[i] = 0.f; }
    if (i >= NN_ * F_) return;
    float v = x[i];
    __nv_bfloat16 h = __float2bfloat16(v);
    g_bfh[i] = h;
    g_bfl[i] = __float2bfloat16(v - __bfloat162float(h));
}

// ---------------- per-dst online softmax + aggregation ----------------------
// mode 0: fp16 h gather, relu, no z output. mode 1: fp32 h gather, tanh, z out.
__device__ __forceinline__ float leaky(float x) {
    return x > 0.f ? x : LEAKY * x;
}

__global__ __launch_bounds__(256) void aggregate(
    const float* __restrict__ bias, float* __restrict__ zout,
    const float* __restrict__ rals, const float* __restrict__ rald,
    float* __restrict__ zals, float* __restrict__ zald, int mode)
{
    __shared__ float swm[8][H_], sws[8][H_];
    __shared__ float s_m[H_], s_inv[H_];
    __shared__ float alpha_sh[CH][H_];
    __shared__ int   src_sh[CH];

    int n = blockIdx.x, tid = threadIdx.x;
    int wid = tid >> 5, lane = tid & 31;
    int beg = g_off[n];
    int deg = g_off[n + 1] - beg;

    // zero the NEXT layer's attn accumulator entries for this node
    if (zals != nullptr && tid < H_) {
        zals[n * H_ + tid] = 0.f;
        zald[n * H_ + tid] = 0.f;
    }

    float ald[H_];
#pragma unroll
    for (int h = 0; h < H_; h++) ald[h] = rald[n * H_ + h];

    float m[H_], s[H_];
#pragma unroll
    for (int h = 0; h < H_; h++) { m[h] = -1e30f; s[h] = 0.f; }
    for (int i = tid; i < deg; i += 256) {
        int sc = g_srcs[beg + i];
#pragma unroll
        for (int h = 0; h < H_; h++) {
            float e = leaky(rals[sc * H_ + h] + ald[h]);
            if (e > m[h]) { s[h] = s[h] * __expf(m[h] - e) + 1.f; m[h] = e; }
            else          s[h] += __expf(e - m[h]);
        }
    }
#pragma unroll
    for (int o = 16; o; o >>= 1) {
#pragma unroll
        for (int h = 0; h < H_; h++) {
            float mo = __shfl_down_sync(0xffffffffu, m[h], o);
            float so = __shfl_down_sync(0xffffffffu, s[h], o);
            float mn = fmaxf(m[h], mo);
            s[h] = s[h] * __expf(m[h] - mn) + so * __expf(mo - mn);
            m[h] = mn;
        }
    }
    if (lane == 0)
#pragma unroll
        for (int h = 0; h < H_; h++) { swm[wid][h] = m[h]; sws[wid][h] = s[h]; }
    __syncthreads();
    if (tid < 32) {
        bool v = lane < 8;
#pragma unroll
        for (int h = 0; h < H_; h++) {
            m[h] = v ? swm[lane][h] : -1e30f;
            s[h] = v ? sws[lane][h] : 0.f;
        }
#pragma unroll
        for (int o = 4; o; o >>= 1) {
#pragma unroll
            for (int h = 0; h < H_; h++) {
                float mo = __shfl_down_sync(0xffffffffu, m[h], o);
                float so = __shfl_down_sync(0xffffffffu, s[h], o);
                float mn = fmaxf(m[h], mo);
                s[h] = s[h] * __expf(m[h] - mn) + so * __expf(mo - mn);
                m[h] = mn;
            }
        }
        if (lane == 0)
#pragma unroll
            for (int h = 0; h < H_; h++) {
                s_m[h]   = m[h];
                s_inv[h] = 1.f / (s[h] + 1e-16f);
            }
    }
    __syncthreads();

    float sm_r[H_], si_r[H_];
#pragma unroll
    for (int h = 0; h < H_; h++) { sm_r[h] = s_m[h]; si_r[h] = s_inv[h]; }

    float acc[H_] = {0.f, 0.f, 0.f, 0.f};
    for (int base = 0; base < deg; base += CH) {
        int c = min(CH, deg - base);
        __syncthreads();
        for (int i = tid; i < c; i += 256) {
            int sc = g_srcs[beg + base + i];
            src_sh[i] = sc;
#pragma unroll
            for (int h = 0; h < H_; h++) {
                float e = leaky(rals[sc * H_ + h] + ald[h]);
                alpha_sh[i][h] = __expf(e - sm_r[h]) * si_r[h];
            }
        }
        __syncthreads();
        if (mode == 0) {
            int j = 0;
            for (; j + 4 <= c; j += 4) {
                int s0 = src_sh[j],     s1 = src_sh[j + 1];
                int s2 = src_sh[j + 2], s3 = src_sh[j + 3];
                const __half* h0 = &g_h16[(size_t)s0 * HF_ + tid];
                const __half* h1 = &g_h16[(size_t)s1 * HF_ + tid];
                const __half* h2 = &g_h16[(size_t)s2 * HF_ + tid];
                const __half* h3 = &g_h16[(size_t)s3 * HF_ + tid];
#pragma unroll
                for (int h = 0; h < H_; h++) {
                    acc[h] += alpha_sh[j][h]     * __half2float(h0[h * F_])
                            + alpha_sh[j + 1][h] * __half2float(h1[h * F_])
                            + alpha_sh[j + 2][h] * __half2float(h2[h * F_])
                            + alpha_sh[j + 3][h] * __half2float(h3[h * F_]);
                }
            }
            for (; j < c; j++) {
                int s0 = src_sh[j];
                const __half* h0 = &g_h16[(size_t)s0 * HF_ + tid];
#pragma unroll
                for (int h = 0; h < H_; h++)
                    acc[h] += alpha_sh[j][h] * __half2float(h0[h * F_]);
            }
        } else {
            int j = 0;
            for (; j + 4 <= c; j += 4) {
                int s0 = src_sh[j],     s1 = src_sh[j + 1];
                int s2 = src_sh[j + 2], s3 = src_sh[j + 3];
                const float* h0 = &g_h[(size_t)s0 * HF_ + tid];
                const float* h1 = &g_h[(size_t)s1 * HF_ + tid];
                const float* h2 = &g_h[(size_t)s2 * HF_ + tid];
                const float* h3 = &g_h[(size_t)s3 * HF_ + tid];
#pragma unroll
                for (int h = 0; h < H_; h++) {
                    acc[h] += alpha_sh[j][h]     * h0[h * F_]
                            + alpha_sh[j + 1][h] * h1[h * F_]
                            + alpha_sh[j + 2][h] * h2[h * F_]
                            + alpha_sh[j + 3][h] * h3[h * F_];
                }
            }
            for (; j < c; j++) {
                int s0 = src_sh[j];
                const float* h0 = &g_h[(size_t)s0 * HF_ + tid];
#pragma unroll
                for (int h = 0; h < H_; h++)
                    acc[h] += alpha_sh[j][h] * h0[h * F_];
            }
        }
    }

    float v = (acc[0] + acc[1] + acc[2] + acc[3]) * 0.25f + bias[tid];
    v = mode ? tanhf(v) : fmaxf(v, 0.f);
    size_t o = (size_t)n * F_ + tid;
    if (mode) zout[o] = v;
    __nv_bfloat16 hh = __float2bfloat16(v);
    g_bfh[o] = hh;
    g_bfl[o] = __float2bfloat16(v - __bfloat162float(hh));
}

// ---------------- driver ----------------------------------------------------
extern "C" void kernel_launch(void* const* d_in, const int* in_sizes, int n_in,
                              void* d_out, int out_size)
{
    const float* x  = (const float*)d_in[0];
    const int*   ei = (const int*)d_in[1];
    const float* W[4];  const float* as_[4]; const float* ad_[4]; const float* b_[4];
    for (int l = 0; l < 4; l++) {
        W[l]   = (const float*)d_in[2 + 4 * l];
        as_[l] = (const float*)d_in[3 + 4 * l];
        ad_[l] = (const float*)d_in[4 + 4 * l];
        b_[l]  = (const float*)d_in[5 + 4 * l];
    }
    float* out = (float*)d_out;

    float *p_h, *p_z, *p_als, *p_ald;
    __half* p_h16;
    __nv_bfloat16 *p_bfh, *p_bfl, *p_wth, *p_wtl;
    cudaGetSymbolAddress((void**)&p_h,    g_h);
    cudaGetSymbolAddress((void**)&p_h16,  g_h16);
    cudaGetSymbolAddress((void**)&p_z,    g_zbuf);
    cudaGetSymbolAddress((void**)&p_als,  g_als);
    cudaGetSymbolAddress((void**)&p_ald,  g_ald);
    cudaGetSymbolAddress((void**)&p_bfh,  g_bfh);
    cudaGetSymbolAddress((void**)&p_bfl,  g_bfl);
    cudaGetSymbolAddress((void**)&p_wth,  g_wth);
    cudaGetSymbolAddress((void**)&p_wtl,  g_wtl);

    const size_t ADJ = (size_t)NN_ * NN_;
    bool z_in_out = ((size_t)out_size >= ADJ + (size_t)NN_ * F_);
    float* zptr = z_in_out ? (out + ADJ) : p_z;

    static bool smem_attr = false;
    if (!smem_attr) {
        cudaFuncSetAttribute(hmma_tt, cudaFuncAttributeMaxDynamicSharedMemorySize,
                             NSTAGE * GBUF);
        smem_attr = true;
    }

    dim3 lgrid(HF_ / 128, (NN_ + 127) / 128);
    const int BUF = NN_ * H_;
    const size_t WOF = (size_t)HF_ * F_;

    // ---- prologue: splits + zeroing, all 4 weight splits ----
    split_x<<<(NN_ * F_ + 255) / 256, 256>>>(x);
    wt_split_all<<<dim3(32, 8, 4), dim3(32, 8)>>>(W[0], W[1], W[2], W[3]);

    // ---- layer 0 GEMM ----
    hmma_tt<<<lgrid, 256, NSTAGE * GBUF>>>(
        p_bfh, p_bfl, p_wth, p_wtl, as_[0], ad_[0],
        p_als, p_ald, nullptr, p_h16, NN_, HF_, HF_, 0);

    // ---- CSR build ----
    count_kernel<<<(ETOT + 255) / 256, 256>>>(ei);
    scan_kernel<<<1, 1024>>>();
    scatter_kernel<<<(ETOT + 255) / 256, 256>>>(ei);

    // ---- A0 (reads buf0, zeroes buf1) ----
    aggregate<<<NN_, 256>>>(b_[0], nullptr, p_als, p_ald,
                            p_als + BUF, p_ald + BUF, 0);

    // ---- layers 1..3 ----
    for (int l = 1; l < 4; l++) {
        int rb = (l & 1) * BUF;
        int zb = ((l + 1) & 1) * BUF;
        int md = (l == 3) ? 1 : 0;
        hmma_tt<<<lgrid, 256, NSTAGE * GBUF>>>(
            p_bfh, p_bfl, p_wth + (size_t)l * WOF, p_wtl + (size_t)l * WOF,
            as_[l], ad_[l], p_als + rb, p_ald + rb,
            md ? p_h : nullptr, p_h16, NN_, HF_, HF_, md);
        aggregate<<<NN_, 256>>>(b_[l], md ? zptr : nullptr,
                                p_als + rb, p_ald + rb,
                                (l < 3) ? p_als + zb : nullptr,
                                (l < 3) ? p_ald + zb : nullptr, md);
    }

    // ---- adj_recon = sigmoid(z @ z^T), triangular grid + mirror ----
    hmma_tt<<<TRI, 256, NSTAGE * GBUF>>>(p_bfh, p_bfl, p_bfh, p_bfl,
                                         nullptr, nullptr, nullptr, nullptr,
                                         out, nullptr, NN_, NN_, NN_, 2);
}